// round 14
// baseline (speedup 1.0000x reference)
#include <cuda_runtime.h>
#include <math.h>

#define Bn    16
#define Cn    256
#define Hn    128
#define Wn    128
#define HWn   (Hn * Wn)     // 16384
#define Kn    300
#define GPB   (HWn / 4)     // 4096 float4 pixel-groups per batch
#define BPB   9             // selection blocks per batch (16*9 = 144 = 1 wave)
#define GSP   455           // groups per block (blocks 0..7), block 8 gets 456
#define SCAP  384           // per-block candidate capacity (expect ~302)
#define CAPF  384           // final candidate capacity (expect ~302)
#define NS2   7             // stage2 slots per thread: ceil(9*384/512)

// Scratch (allocation-free rule: __device__ globals). ~3.2 MB -> L2-resident.
__device__ float    g_reg0 [Bn * HWn];
__device__ float    g_reg1 [Bn * HWn];
__device__ float    g_conf [Bn * HWn];
__device__ unsigned long long g_cand[Bn * BPB * SCAP];
__device__ int                g_ccnt[Bn * BPB];

// ---------------------------------------------------------------------------
// Pass 1 (fused): 1x1 convs + sigmoid + score + PER-BLOCK top-300 selection.
// Grid 16 batches x 9 blocks = 144 blocks (one balanced wave, 1 block/SM),
// 512 threads, one float4 pixel-group per thread (455-456 groups per block,
// never crossing a batch boundary). After the HBM-bound streaming part, each
// block runs a 10-round 3-bit multiway radix bisection over its ~1820 score
// bit patterns (register-resident; scores >= 0 so uint order == value order)
// and emits a superset of its local top-300 -> superset of the batch top-300.
// This removes the g_sbits global round-trip AND one kernel launch.
// ---------------------------------------------------------------------------
__global__ __launch_bounds__(512) void score_sel_kernel(
    const float* __restrict__ x,
    const float* __restrict__ w_reg,
    const float* __restrict__ b_reg,
    const float* __restrict__ w_conf,
    const float* __restrict__ b_conf)
{
    __shared__ float    wr0[Cn], wr1[Cn], wc[Cn];
    __shared__ uint4    wredv[16];
    __shared__ unsigned sP;
    __shared__ int      s_m;

    const int tid  = threadIdx.x;
    const int wid  = tid >> 5;
    const int lane = tid & 31;
    const int b    = blockIdx.x / BPB;
    const int blk9 = blockIdx.x - b * BPB;
    const int s    = blk9 * GSP;
    const int e    = (blk9 == BPB - 1) ? GPB : (s + GSP);
    const int g    = s + tid;                 // this thread's group (if valid)
    const bool valid = (g < e);

    if (tid == 0) s_m = 0;
    if (tid < Cn) {
        wr0[tid] = w_reg[tid];
        wr1[tid] = w_reg[Cn + tid];
        wc[tid]  = w_conf[tid];
    }
    __syncthreads();

    uint4 sbv = make_uint4(0u, 0u, 0u, 0u);   // score bits (0 for idle threads)

    if (valid) {
        const float4* xp = reinterpret_cast<const float4*>(x)
                           + (size_t)b * Cn * GPB + g;

        float4 a0 = make_float4(0.f, 0.f, 0.f, 0.f);
        float4 a1 = make_float4(0.f, 0.f, 0.f, 0.f);
        float4 a2 = make_float4(0.f, 0.f, 0.f, 0.f);

        #pragma unroll 8
        for (int c = 0; c < Cn; ++c) {
            // evict-first streaming load: don't thrash L2 (scratch lives there)
            float4 xv = __ldcs(&xp[(size_t)c * GPB]);
            float u0 = wr0[c], u1 = wr1[c], u2 = wc[c];
            a0.x = fmaf(xv.x, u0, a0.x); a0.y = fmaf(xv.y, u0, a0.y);
            a0.z = fmaf(xv.z, u0, a0.z); a0.w = fmaf(xv.w, u0, a0.w);
            a1.x = fmaf(xv.x, u1, a1.x); a1.y = fmaf(xv.y, u1, a1.y);
            a1.z = fmaf(xv.z, u1, a1.z); a1.w = fmaf(xv.w, u1, a1.w);
            a2.x = fmaf(xv.x, u2, a2.x); a2.y = fmaf(xv.y, u2, a2.y);
            a2.z = fmaf(xv.z, u2, a2.z); a2.w = fmaf(xv.w, u2, a2.w);
        }

        const float br0 = __ldg(b_reg), br1 = __ldg(b_reg + 1), bc = __ldg(b_conf);

        float4 r0v, r1v, cfv;
        const float* p0 = &a0.x; const float* p1 = &a1.x; const float* p2 = &a2.x;
        float*       q0 = &r0v.x; float*      q1 = &r1v.x; float*      qc = &cfv.x;
        unsigned*    qs = &sbv.x;
        #pragma unroll
        for (int i = 0; i < 4; ++i) {
            float r0 = p0[i] + br0;
            float r1 = p1[i] + br1;
            float cf = 1.0f / (1.0f + expf(-(p2[i] + bc)));
            float sc = sqrtf(fmaf(r0, r0, r1 * r1)) * cf;
            q0[i] = r0; q1[i] = r1; qc[i] = cf; qs[i] = __float_as_uint(sc);
        }

        const int v = b * GPB + g;            // float4-granular index
        reinterpret_cast<float4*>(g_reg0)[v] = r0v;
        reinterpret_cast<float4*>(g_reg1)[v] = r1v;
        reinterpret_cast<float4*>(g_conf)[v] = cfv;
    }

    // ---- per-block top-300 threshold: 10 rounds x 3 bits, 7 thresholds ----
    // Idle threads participate with zero values (full-mask REDUX/barriers).
    unsigned P = 0u;
    #pragma unroll
    for (int sh = 29; sh >= 2; sh -= 3) {
        const unsigned T1 = P | (1u << sh), T2 = P | (2u << sh),
                       T3 = P | (3u << sh), T4 = P | (4u << sh),
                       T5 = P | (5u << sh), T6 = P | (6u << sh),
                       T7 = P | (7u << sh);
        int c1=0,c2=0,c3=0,c4=0,c5=0,c6=0,c7=0;
        {
            const unsigned* vv = &sbv.x;
            #pragma unroll
            for (int j = 0; j < 4; ++j) {
                const unsigned xv = vv[j];
                c1 += (xv >= T1); c2 += (xv >= T2); c3 += (xv >= T3);
                c4 += (xv >= T4); c5 += (xv >= T5); c6 += (xv >= T6);
                c7 += (xv >= T7);
            }
        }
        unsigned p0 = (unsigned)c1 | ((unsigned)c2 << 16);
        unsigned p1 = (unsigned)c3 | ((unsigned)c4 << 16);
        unsigned p2 = (unsigned)c5 | ((unsigned)c6 << 16);
        unsigned p3 = (unsigned)c7;
        p0 = __reduce_add_sync(0xFFFFFFFFu, p0);   // fields <= 128: no carry
        p1 = __reduce_add_sync(0xFFFFFFFFu, p1);
        p2 = __reduce_add_sync(0xFFFFFFFFu, p2);
        p3 = __reduce_add_sync(0xFFFFFFFFu, p3);
        if (lane == 0) wredv[wid] = make_uint4(p0, p1, p2, p3);
        __syncthreads();
        if (wid == 0) {
            uint4 q = (lane < 16) ? wredv[lane] : make_uint4(0, 0, 0, 0);
            #pragma unroll
            for (int d = 1; d < 16; d <<= 1) {     // closed within groups of 16
                q.x += __shfl_xor_sync(0xFFFFFFFFu, q.x, d);
                q.y += __shfl_xor_sync(0xFFFFFFFFu, q.y, d);
                q.z += __shfl_xor_sync(0xFFFFFFFFu, q.z, d);
                q.w += __shfl_xor_sync(0xFFFFFFFFu, q.w, d);
            }
            if (lane == 0) {                       // fields <= 2048: no carry
                const int C1 = (int)(q.x & 0xFFFFu), C2 = (int)(q.x >> 16);
                const int C3 = (int)(q.y & 0xFFFFu), C4 = (int)(q.y >> 16);
                const int C5 = (int)(q.z & 0xFFFFu), C6 = (int)(q.z >> 16);
                const int C7 = (int)q.w;
                int jj;                            // C1>=C2>=...>=C7
                if (C4 >= Kn) jj = (C6 >= Kn) ? ((C7 >= Kn) ? 7 : 6)
                                              : ((C5 >= Kn) ? 5 : 4);
                else          jj = (C2 >= Kn) ? ((C3 >= Kn) ? 3 : 2)
                                              : ((C1 >= Kn) ? 1 : 0);
                sP = P | ((unsigned)jj << sh);
            }
        }
        __syncthreads();
        P = sP;
    }

    // ---- emit survivors (warp-aggregated atomic; ~302 expected) ----
    unsigned long long* cd = g_cand + (size_t)(b * BPB + blk9) * SCAP;
    if (valid) {
        const unsigned* vv = &sbv.x;
        #pragma unroll
        for (int i = 0; i < 4; ++i) {
            if (vv[i] >= P) {
                const int p = atomicAdd(&s_m, 1);
                if (p < SCAP) {
                    const int idx = g * 4 + i;         // batch-local pixel idx
                    cd[p] = ((unsigned long long)vv[i] << 32)
                          | (unsigned)(HWn - idx);     // smaller idx => bigger key
                }
            }
        }
    }
    __syncthreads();
    if (tid == 0) g_ccnt[b * BPB + blk9] = (s_m < SCAP) ? s_m : SCAP;
}

// ---------------------------------------------------------------------------
// Pass 2: 16 blocks x 512 threads. Loads the ~9*302 candidates of its batch
// into registers (7 fixed slots/thread over the 9*SCAP layout, zero-padded),
// runs the same 10-round multiway bisection for the global batch threshold,
// then an exact stable O(M^2) rank sort (M ~ 302) on 64-bit keys and the
// gather/write. jax.lax.top_k semantics: descending value, ties -> lower
// index (encoded in the key low word).
// ---------------------------------------------------------------------------
__global__ __launch_bounds__(512) void topk_stage2(float* __restrict__ out)
{
    const int b    = blockIdx.x;
    const int tid  = threadIdx.x;
    const int wid  = tid >> 5;
    const int lane = tid & 31;

    __shared__ uint4    wredv[16];
    __shared__ int      cnt9[BPB];
    __shared__ unsigned sP;
    __shared__ int      s_m;
    __shared__ unsigned long long ckey[CAPF];

    if (tid == 0)  s_m = 0;
    if (tid < BPB) cnt9[tid] = g_ccnt[b * BPB + tid];
    __syncthreads();

    unsigned uh[NS2], ul[NS2];
    #pragma unroll
    for (int j = 0; j < NS2; ++j) {
        const int slot = tid + 512 * j;              // < 3584; layout is 3456
        unsigned long long k = 0ULL;
        if (slot < BPB * SCAP) {
            const int sg  = slot / SCAP;
            const int pos = slot - sg * SCAP;
            if (pos < cnt9[sg])
                k = g_cand[(size_t)(b * BPB + sg) * SCAP + pos];
        }
        uh[j] = (unsigned)(k >> 32);
        ul[j] = (unsigned)k;
    }

    unsigned P = 0u;
    #pragma unroll
    for (int sh = 29; sh >= 2; sh -= 3) {
        const unsigned T1 = P | (1u << sh), T2 = P | (2u << sh),
                       T3 = P | (3u << sh), T4 = P | (4u << sh),
                       T5 = P | (5u << sh), T6 = P | (6u << sh),
                       T7 = P | (7u << sh);
        int c1=0,c2=0,c3=0,c4=0,c5=0,c6=0,c7=0;
        #pragma unroll
        for (int j = 0; j < NS2; ++j) {
            const unsigned xv = uh[j];
            c1 += (xv >= T1); c2 += (xv >= T2); c3 += (xv >= T3);
            c4 += (xv >= T4); c5 += (xv >= T5); c6 += (xv >= T6);
            c7 += (xv >= T7);
        }
        unsigned p0 = (unsigned)c1 | ((unsigned)c2 << 16);
        unsigned p1 = (unsigned)c3 | ((unsigned)c4 << 16);
        unsigned p2 = (unsigned)c5 | ((unsigned)c6 << 16);
        unsigned p3 = (unsigned)c7;
        p0 = __reduce_add_sync(0xFFFFFFFFu, p0);
        p1 = __reduce_add_sync(0xFFFFFFFFu, p1);
        p2 = __reduce_add_sync(0xFFFFFFFFu, p2);
        p3 = __reduce_add_sync(0xFFFFFFFFu, p3);
        if (lane == 0) wredv[wid] = make_uint4(p0, p1, p2, p3);
        __syncthreads();
        if (wid == 0) {
            uint4 q = (lane < 16) ? wredv[lane] : make_uint4(0, 0, 0, 0);
            #pragma unroll
            for (int d = 1; d < 16; d <<= 1) {      // closed within groups of 16
                q.x += __shfl_xor_sync(0xFFFFFFFFu, q.x, d);
                q.y += __shfl_xor_sync(0xFFFFFFFFu, q.y, d);
                q.z += __shfl_xor_sync(0xFFFFFFFFu, q.z, d);
                q.w += __shfl_xor_sync(0xFFFFFFFFu, q.w, d);
            }
            if (lane == 0) {                        // fields <= 3584: no carry
                const int C1 = (int)(q.x & 0xFFFFu), C2 = (int)(q.x >> 16);
                const int C3 = (int)(q.y & 0xFFFFu), C4 = (int)(q.y >> 16);
                const int C5 = (int)(q.z & 0xFFFFu), C6 = (int)(q.z >> 16);
                const int C7 = (int)q.w;
                int jj;
                if (C4 >= Kn) jj = (C6 >= Kn) ? ((C7 >= Kn) ? 7 : 6)
                                              : ((C5 >= Kn) ? 5 : 4);
                else          jj = (C2 >= Kn) ? ((C3 >= Kn) ? 3 : 2)
                                              : ((C1 >= Kn) ? 1 : 0);
                sP = P | ((unsigned)jj << sh);
            }
        }
        __syncthreads();
        P = sP;
    }

    // ---- collect final candidates (>= P; ul!=0 excludes padding) ----
    #pragma unroll
    for (int j = 0; j < NS2; ++j) {
        if (uh[j] >= P && ul[j]) {
            const int p = atomicAdd(&s_m, 1);
            if (p < CAPF)
                ckey[p] = ((unsigned long long)uh[j] << 32) | ul[j];
        }
    }
    __syncthreads();
    const int M = (s_m < CAPF) ? s_m : CAPF;

    // ---- stable rank sort (broadcast SMEM reads) + gather + write ----
    for (int i = tid; i < M; i += 512) {
        const unsigned long long mk = ckey[i];
        int rank = 0;
        #pragma unroll 4
        for (int j = 0; j < M; ++j) rank += (ckey[j] > mk);
        if (rank < Kn) {
            const int k = HWn - (int)(mk & 0xFFFFFFFFu);
            float* o = out + ((size_t)b * Kn + rank) * 3;
            o[0] = (float)(k / Hn) + g_reg0[b * HWn + k];
            o[1] = (float)(k % Hn) + g_reg1[b * HWn + k];
            o[2] = g_conf[b * HWn + k];
        }
    }
}

// ---------------------------------------------------------------------------
extern "C" void kernel_launch(void* const* d_in, const int* in_sizes, int n_in,
                              void* d_out, int out_size)
{
    const float* x      = (const float*)d_in[0];  // (16,256,128,128)
    const float* w_reg  = (const float*)d_in[1];  // (2,256)
    const float* b_reg  = (const float*)d_in[2];  // (2,)
    const float* w_conf = (const float*)d_in[3];  // (1,256)
    const float* b_conf = (const float*)d_in[4];  // (1,)
    float*       out    = (float*)d_out;          // (16,300,3)

    score_sel_kernel<<<Bn * BPB, 512>>>(x, w_reg, b_reg, w_conf, b_conf);
    topk_stage2<<<Bn, 512>>>(out);
}

// round 15
// speedup vs baseline: 1.0413x; 1.0413x over previous
#include <cuda_runtime.h>
#include <math.h>

#define Bn    16
#define Cn    256
#define Hn    128
#define Wn    128
#define HWn   (Hn * Wn)     // 16384
#define Kn    300
#define GPB   (HWn / 4)     // 4096 float4 pixel-groups per batch
#define BPB   9             // blocks per batch (16*9 = 144 blocks, 1 wave)
#define GSP   456           // groups per block 0..7 (57*8: 128B-aligned spans)
#define SCAP  384           // per-block candidate capacity (expect ~302)

// Scratch (allocation-free rule: __device__ globals). ~1.8 MB -> L2-resident.
__device__ unsigned long long g_ckey[Bn * BPB * SCAP];  // sorted desc per block
__device__ float              g_cr0 [Bn * BPB * SCAP];
__device__ float              g_cr1 [Bn * BPB * SCAP];
__device__ float              g_ccf [Bn * BPB * SCAP];
__device__ int                g_ccnt[Bn * BPB];

// ---------------------------------------------------------------------------
// Pass 1 (fused): 1x1 convs + sigmoid + score + per-block top-300 selection
// + per-block SORT. 144 blocks x 512 threads, one float4 group per thread,
// spans of 456 groups (mult of 8 -> every warp's 512B load is 128B-sector-
// aligned; the 455-span version cost +25% DRAM sectors). After the HBM-bound
// stream, a 10-round 3-bit multiway radix bisection (scores >= 0 so uint
// order == value order) finds the block-local top-300 threshold (superset of
// this segment's global-top-300 members); survivors + payload (r0,r1,conf)
// go to SMEM, get rank-sorted (M ~ 302, broadcast LDS), and are written to
// global as a DESC-sorted list. No full score/reg/conf maps ever hit DRAM.
// ---------------------------------------------------------------------------
__global__ __launch_bounds__(512) void score_sel_kernel(
    const float* __restrict__ x,
    const float* __restrict__ w_reg,
    const float* __restrict__ b_reg,
    const float* __restrict__ w_conf,
    const float* __restrict__ b_conf)
{
    __shared__ float    wr0[Cn], wr1[Cn], wc[Cn];
    __shared__ uint4    wredv[16];
    __shared__ unsigned sP;
    __shared__ int      s_m;
    __shared__ unsigned long long skey[SCAP];
    __shared__ float    sr0[SCAP], sr1[SCAP], scf[SCAP];

    const int tid  = threadIdx.x;
    const int wid  = tid >> 5;
    const int lane = tid & 31;
    const int b    = blockIdx.x / BPB;
    const int blk9 = blockIdx.x - b * BPB;
    const int s    = blk9 * GSP;
    const int span = (blk9 == BPB - 1) ? (GPB - 8 * GSP) : GSP;  // 448 or 456
    const int g    = s + tid;
    const bool valid = (tid < span);

    if (tid == 0) s_m = 0;
    if (tid < Cn) {
        wr0[tid] = w_reg[tid];
        wr1[tid] = w_reg[Cn + tid];
        wc[tid]  = w_conf[tid];
    }
    __syncthreads();

    uint4  sbv = make_uint4(0u, 0u, 0u, 0u);   // score bits (0 for idle)
    float4 r0v, r1v, cfv;                      // payload kept in registers

    if (valid) {
        const float4* xp = reinterpret_cast<const float4*>(x)
                           + (size_t)b * Cn * GPB + g;

        float4 a0 = make_float4(0.f, 0.f, 0.f, 0.f);
        float4 a1 = make_float4(0.f, 0.f, 0.f, 0.f);
        float4 a2 = make_float4(0.f, 0.f, 0.f, 0.f);

        #pragma unroll 8
        for (int c = 0; c < Cn; ++c) {
            // evict-first streaming load: 268MB stream must not thrash L2
            float4 xv = __ldcs(&xp[(size_t)c * GPB]);
            float u0 = wr0[c], u1 = wr1[c], u2 = wc[c];
            a0.x = fmaf(xv.x, u0, a0.x); a0.y = fmaf(xv.y, u0, a0.y);
            a0.z = fmaf(xv.z, u0, a0.z); a0.w = fmaf(xv.w, u0, a0.w);
            a1.x = fmaf(xv.x, u1, a1.x); a1.y = fmaf(xv.y, u1, a1.y);
            a1.z = fmaf(xv.z, u1, a1.z); a1.w = fmaf(xv.w, u1, a1.w);
            a2.x = fmaf(xv.x, u2, a2.x); a2.y = fmaf(xv.y, u2, a2.y);
            a2.z = fmaf(xv.z, u2, a2.z); a2.w = fmaf(xv.w, u2, a2.w);
        }

        const float br0 = __ldg(b_reg), br1 = __ldg(b_reg + 1), bc = __ldg(b_conf);

        const float* p0 = &a0.x; const float* p1 = &a1.x; const float* p2 = &a2.x;
        float*       q0 = &r0v.x; float*      q1 = &r1v.x; float*      qc = &cfv.x;
        unsigned*    qs = &sbv.x;
        #pragma unroll
        for (int i = 0; i < 4; ++i) {
            float r0 = p0[i] + br0;
            float r1 = p1[i] + br1;
            float cf = 1.0f / (1.0f + expf(-(p2[i] + bc)));
            float sc = sqrtf(fmaf(r0, r0, r1 * r1)) * cf;
            q0[i] = r0; q1[i] = r1; qc[i] = cf; qs[i] = __float_as_uint(sc);
        }
    }

    // ---- per-block top-300 threshold: 10 rounds x 3 bits, 7 thresholds ----
    unsigned P = 0u;
    #pragma unroll
    for (int sh = 29; sh >= 2; sh -= 3) {
        const unsigned T1 = P | (1u << sh), T2 = P | (2u << sh),
                       T3 = P | (3u << sh), T4 = P | (4u << sh),
                       T5 = P | (5u << sh), T6 = P | (6u << sh),
                       T7 = P | (7u << sh);
        int c1=0,c2=0,c3=0,c4=0,c5=0,c6=0,c7=0;
        {
            const unsigned* vv = &sbv.x;
            #pragma unroll
            for (int j = 0; j < 4; ++j) {
                const unsigned xv = vv[j];
                c1 += (xv >= T1); c2 += (xv >= T2); c3 += (xv >= T3);
                c4 += (xv >= T4); c5 += (xv >= T5); c6 += (xv >= T6);
                c7 += (xv >= T7);
            }
        }
        unsigned p0 = (unsigned)c1 | ((unsigned)c2 << 16);
        unsigned p1 = (unsigned)c3 | ((unsigned)c4 << 16);
        unsigned p2 = (unsigned)c5 | ((unsigned)c6 << 16);
        unsigned p3 = (unsigned)c7;
        p0 = __reduce_add_sync(0xFFFFFFFFu, p0);   // fields <= 128: no carry
        p1 = __reduce_add_sync(0xFFFFFFFFu, p1);
        p2 = __reduce_add_sync(0xFFFFFFFFu, p2);
        p3 = __reduce_add_sync(0xFFFFFFFFu, p3);
        if (lane == 0) wredv[wid] = make_uint4(p0, p1, p2, p3);
        __syncthreads();
        if (wid == 0) {
            uint4 q = (lane < 16) ? wredv[lane] : make_uint4(0, 0, 0, 0);
            #pragma unroll
            for (int d = 1; d < 16; d <<= 1) {     // closed within groups of 16
                q.x += __shfl_xor_sync(0xFFFFFFFFu, q.x, d);
                q.y += __shfl_xor_sync(0xFFFFFFFFu, q.y, d);
                q.z += __shfl_xor_sync(0xFFFFFFFFu, q.z, d);
                q.w += __shfl_xor_sync(0xFFFFFFFFu, q.w, d);
            }
            if (lane == 0) {                       // fields <= 2048: no carry
                const int C1 = (int)(q.x & 0xFFFFu), C2 = (int)(q.x >> 16);
                const int C3 = (int)(q.y & 0xFFFFu), C4 = (int)(q.y >> 16);
                const int C5 = (int)(q.z & 0xFFFFu), C6 = (int)(q.z >> 16);
                const int C7 = (int)q.w;
                int jj;                            // C1>=C2>=...>=C7
                if (C4 >= Kn) jj = (C6 >= Kn) ? ((C7 >= Kn) ? 7 : 6)
                                              : ((C5 >= Kn) ? 5 : 4);
                else          jj = (C2 >= Kn) ? ((C3 >= Kn) ? 3 : 2)
                                              : ((C1 >= Kn) ? 1 : 0);
                sP = P | ((unsigned)jj << sh);
            }
        }
        __syncthreads();
        P = sP;
    }

    // ---- collect survivors + payload into SMEM ----
    if (valid) {
        const unsigned* vv = &sbv.x;
        const float* q0 = &r0v.x; const float* q1 = &r1v.x; const float* qc = &cfv.x;
        #pragma unroll
        for (int i = 0; i < 4; ++i) {
            if (vv[i] >= P) {
                const int p = atomicAdd(&s_m, 1);
                if (p < SCAP) {
                    const int idx = g * 4 + i;          // batch-local pixel idx
                    skey[p] = ((unsigned long long)vv[i] << 32)
                            | (unsigned)(HWn - idx);    // smaller idx => bigger key
                    sr0[p] = q0[i]; sr1[p] = q1[i]; scf[p] = qc[i];
                }
            }
        }
    }
    __syncthreads();
    const int M = (s_m < SCAP) ? s_m : SCAP;

    // ---- rank-sort (keys unique: strict order) + write sorted list ----
    const size_t base = (size_t)(b * BPB + blk9) * SCAP;
    if (tid < M) {
        const unsigned long long mk = skey[tid];
        int rank = 0;
        #pragma unroll 4
        for (int j = 0; j < M; ++j) rank += (skey[j] > mk);
        g_ckey[base + rank] = mk;
        g_cr0 [base + rank] = sr0[tid];
        g_cr1 [base + rank] = sr1[tid];
        g_ccf [base + rank] = scf[tid];
    }
    if (tid == 0) g_ccnt[b * BPB + blk9] = M;
}

// ---------------------------------------------------------------------------
// Pass 2: 16 blocks x 1024 threads, one per batch. Loads the 9 sorted lists
// (~302 each) into SMEM; each element with in-list position < 300 computes
// its EXACT global rank = pos + sum over the other 8 lists of
// count(key > x) via binary search (9 probes/list, descending order, unique
// keys). rank < 300 -> write output row. No bisection, no O(M^2) sort, no
// block-wide reductions: fully parallel, ~3k-cycle serial chain.
// jax.lax.top_k semantics (desc value, ties -> lower index) are encoded in
// the 64-bit key low word.
// ---------------------------------------------------------------------------
__global__ __launch_bounds__(1024) void topk_final(float* __restrict__ out)
{
    const int b   = blockIdx.x;
    const int tid = threadIdx.x;

    __shared__ unsigned long long lst[BPB * SCAP];
    __shared__ int cnt[BPB];

    if (tid < BPB) cnt[tid] = g_ccnt[b * BPB + tid];
    __syncthreads();

    for (int slot = tid; slot < BPB * SCAP; slot += 1024) {
        const int L   = slot / SCAP;
        const int pos = slot - L * SCAP;
        lst[slot] = (pos < cnt[L])
                  ? g_ckey[(size_t)(b * BPB + L) * SCAP + pos] : 0ULL;
    }
    __syncthreads();

    for (int slot = tid; slot < BPB * SCAP; slot += 1024) {
        const int L   = slot / SCAP;
        const int pos = slot - L * SCAP;
        if (pos >= Kn || pos >= cnt[L]) continue;   // rank >= pos: can't win
        const unsigned long long xk = lst[slot];

        int rank = pos;
        #pragma unroll
        for (int L2 = 0; L2 < BPB; ++L2) {
            if (L2 == L) continue;
            int lo = 0, hi = cnt[L2];
            const unsigned long long* ls = lst + L2 * SCAP;
            while (lo < hi) {                       // count of keys > xk
                const int mid = (lo + hi) >> 1;
                if (ls[mid] > xk) lo = mid + 1; else hi = mid;
            }
            rank += lo;
        }

        if (rank < Kn) {
            const int    k    = HWn - (int)(unsigned)xk;
            const size_t base = (size_t)(b * BPB + L) * SCAP + pos;
            float* o = out + ((size_t)b * Kn + rank) * 3;
            o[0] = (float)(k / Hn) + g_cr0[base];
            o[1] = (float)(k % Hn) + g_cr1[base];
            o[2] = g_ccf[base];
        }
    }
}

// ---------------------------------------------------------------------------
extern "C" void kernel_launch(void* const* d_in, const int* in_sizes, int n_in,
                              void* d_out, int out_size)
{
    const float* x      = (const float*)d_in[0];  // (16,256,128,128)
    const float* w_reg  = (const float*)d_in[1];  // (2,256)
    const float* b_reg  = (const float*)d_in[2];  // (2,)
    const float* w_conf = (const float*)d_in[3];  // (1,256)
    const float* b_conf = (const float*)d_in[4];  // (1,)
    float*       out    = (float*)d_out;          // (16,300,3)

    score_sel_kernel<<<Bn * BPB, 512>>>(x, w_reg, b_reg, w_conf, b_conf);
    topk_final<<<Bn, 1024>>>(out);
}

// round 17
// speedup vs baseline: 1.1626x; 1.1165x over previous
#include <cuda_runtime.h>
#include <math.h>

#define Bn    16
#define Cn    256
#define Hn    128
#define Wn    128
#define HWn   (Hn * Wn)     // 16384
#define Kn    300
#define SEGS  8             // segments per batch
#define SEGN  (HWn / SEGS)  // 2048
#define SCAP  384           // per-segment candidate capacity (expect ~302)

// Scratch (allocation-free rule: __device__ globals). ~4.2 MB -> L2-resident.
__device__ float    g_reg0 [Bn * HWn];
__device__ float    g_reg1 [Bn * HWn];
__device__ float    g_conf [Bn * HWn];
__device__ unsigned g_sbits[Bn * HWn];
__device__ unsigned long long g_ckey[Bn * SEGS * SCAP];  // DESC-sorted per seg
__device__ int                g_ccnt[Bn * SEGS];

// ---------------------------------------------------------------------------
// Pass 1: fused 1x1 convs + sigmoid + score. One thread = 4 pixels (float4).
// EXACT R10 configuration (128 blocks x 512 threads, unroll 8): measured
// 61.2us / ~4.5 TB/s — the best score config observed. Do not touch.
// ---------------------------------------------------------------------------
__global__ __launch_bounds__(512) void score_kernel(
    const float* __restrict__ x,
    const float* __restrict__ w_reg,
    const float* __restrict__ b_reg,
    const float* __restrict__ w_conf,
    const float* __restrict__ b_conf)
{
    __shared__ float wr0[Cn], wr1[Cn], wc[Cn];
    if (threadIdx.x < Cn) {
        wr0[threadIdx.x] = w_reg[threadIdx.x];
        wr1[threadIdx.x] = w_reg[Cn + threadIdx.x];
        wc[threadIdx.x]  = w_conf[threadIdx.x];
    }
    __syncthreads();

    const int gid = blockIdx.x * 512 + threadIdx.x;     // pixel-group id
    const int b   = gid >> 12;                          // / (HWn/4)
    const int g   = gid & 4095;                         // % (HWn/4)

    const float4* xp = reinterpret_cast<const float4*>(x)
                       + (size_t)b * Cn * (HWn / 4) + g;

    float4 a0 = make_float4(0.f, 0.f, 0.f, 0.f);
    float4 a1 = make_float4(0.f, 0.f, 0.f, 0.f);
    float4 a2 = make_float4(0.f, 0.f, 0.f, 0.f);

    #pragma unroll 8
    for (int c = 0; c < Cn; ++c) {
        // evict-first streaming load: 268MB stream must not thrash L2
        float4 xv = __ldcs(&xp[(size_t)c * (HWn / 4)]);
        float u0 = wr0[c], u1 = wr1[c], u2 = wc[c];
        a0.x = fmaf(xv.x, u0, a0.x); a0.y = fmaf(xv.y, u0, a0.y);
        a0.z = fmaf(xv.z, u0, a0.z); a0.w = fmaf(xv.w, u0, a0.w);
        a1.x = fmaf(xv.x, u1, a1.x); a1.y = fmaf(xv.y, u1, a1.y);
        a1.z = fmaf(xv.z, u1, a1.z); a1.w = fmaf(xv.w, u1, a1.w);
        a2.x = fmaf(xv.x, u2, a2.x); a2.y = fmaf(xv.y, u2, a2.y);
        a2.z = fmaf(xv.z, u2, a2.z); a2.w = fmaf(xv.w, u2, a2.w);
    }

    const float br0 = __ldg(b_reg), br1 = __ldg(b_reg + 1), bc = __ldg(b_conf);

    float4 r0v, r1v, cfv; uint4 sbv;
    const float* p0 = &a0.x; const float* p1 = &a1.x; const float* p2 = &a2.x;
    float*       q0 = &r0v.x; float*      q1 = &r1v.x; float*      qc = &cfv.x;
    unsigned*    qs = &sbv.x;
    #pragma unroll
    for (int i = 0; i < 4; ++i) {
        float r0 = p0[i] + br0;
        float r1 = p1[i] + br1;
        float cf = 1.0f / (1.0f + expf(-(p2[i] + bc)));
        float sc = sqrtf(fmaf(r0, r0, r1 * r1)) * cf;
        q0[i] = r0; q1[i] = r1; qc[i] = cf; qs[i] = __float_as_uint(sc);
    }

    const int v = b * (HWn / 4) + g;   // float4-granular index
    reinterpret_cast<float4*>(g_reg0)[v] = r0v;
    reinterpret_cast<float4*>(g_reg1)[v] = r1v;
    reinterpret_cast<float4*>(g_conf)[v] = cfv;
    reinterpret_cast<uint4*>(g_sbits)[v] = sbv;
}

// ---------------------------------------------------------------------------
// Stage 1: 128 blocks (16 batches x 8 segments) x 256 threads, 2048 scores
// per block (8/thread, register-resident). 10 rounds x 3 bits multiway radix
// bisection (scores >= 0 so uint order == value order) finds the segment's
// top-300 threshold; invariant count(>=P) >= 300 always holds (jj=0 keeps
// the previous accepted P). Survivors collected in SMEM, rank-sorted (keys
// unique), written to global as a DESC-sorted list. NOTE: all M-dependent
// loops are grid-stride — M (~302) exceeds blockDim (256). R16 failed on
// exactly that (`if (tid < M)` left ~46 unsorted holes per list).
// ---------------------------------------------------------------------------
__global__ __launch_bounds__(256) void topk_stage1()
{
    const int blk  = blockIdx.x;            // 0..127
    const int b    = blk >> 3;
    const int s0   = (blk & 7) * SEGN;
    const int tid  = threadIdx.x;
    const int wid  = tid >> 5;
    const int lane = tid & 31;
    const unsigned* sb = g_sbits + b * HWn + s0;

    __shared__ uint4    wredv[8];
    __shared__ unsigned sP;
    __shared__ int      s_m;
    __shared__ unsigned long long skey[SCAP];

    if (tid == 0) s_m = 0;

    unsigned v[8];
    #pragma unroll
    for (int j = 0; j < 8; ++j) v[j] = sb[tid + 256 * j];   // coalesced

    unsigned P = 0u;
    #pragma unroll
    for (int sh = 29; sh >= 2; sh -= 3) {
        const unsigned T1 = P | (1u << sh), T2 = P | (2u << sh),
                       T3 = P | (3u << sh), T4 = P | (4u << sh),
                       T5 = P | (5u << sh), T6 = P | (6u << sh),
                       T7 = P | (7u << sh);
        int c1=0,c2=0,c3=0,c4=0,c5=0,c6=0,c7=0;
        #pragma unroll
        for (int j = 0; j < 8; ++j) {
            const unsigned xv = v[j];
            c1 += (xv >= T1); c2 += (xv >= T2); c3 += (xv >= T3);
            c4 += (xv >= T4); c5 += (xv >= T5); c6 += (xv >= T6);
            c7 += (xv >= T7);
        }
        unsigned p0 = (unsigned)c1 | ((unsigned)c2 << 16);
        unsigned p1 = (unsigned)c3 | ((unsigned)c4 << 16);
        unsigned p2 = (unsigned)c5 | ((unsigned)c6 << 16);
        unsigned p3 = (unsigned)c7;
        p0 = __reduce_add_sync(0xFFFFFFFFu, p0);   // fields <= 256: no carry
        p1 = __reduce_add_sync(0xFFFFFFFFu, p1);
        p2 = __reduce_add_sync(0xFFFFFFFFu, p2);
        p3 = __reduce_add_sync(0xFFFFFFFFu, p3);
        if (lane == 0) wredv[wid] = make_uint4(p0, p1, p2, p3);
        __syncthreads();
        if (wid == 0) {
            uint4 q = (lane < 8) ? wredv[lane] : make_uint4(0, 0, 0, 0);
            #pragma unroll
            for (int d = 1; d < 8; d <<= 1) {       // closed within groups of 8
                q.x += __shfl_xor_sync(0xFFFFFFFFu, q.x, d);
                q.y += __shfl_xor_sync(0xFFFFFFFFu, q.y, d);
                q.z += __shfl_xor_sync(0xFFFFFFFFu, q.z, d);
                q.w += __shfl_xor_sync(0xFFFFFFFFu, q.w, d);
            }
            if (lane == 0) {                        // fields <= 2048: no carry
                const int C1 = (int)(q.x & 0xFFFFu), C2 = (int)(q.x >> 16);
                const int C3 = (int)(q.y & 0xFFFFu), C4 = (int)(q.y >> 16);
                const int C5 = (int)(q.z & 0xFFFFu), C6 = (int)(q.z >> 16);
                const int C7 = (int)q.w;
                int jj;                              // C1>=C2>=...>=C7
                if (C4 >= Kn) jj = (C6 >= Kn) ? ((C7 >= Kn) ? 7 : 6)
                                              : ((C5 >= Kn) ? 5 : 4);
                else          jj = (C2 >= Kn) ? ((C3 >= Kn) ? 3 : 2)
                                              : ((C1 >= Kn) ? 1 : 0);
                sP = P | ((unsigned)jj << sh);
            }
        }
        __syncthreads();
        P = sP;
    }

    // ---- collect survivors into SMEM (warp-aggregated atomic) ----
    #pragma unroll
    for (int j = 0; j < 8; ++j) {
        if (v[j] >= P) {
            const int p = atomicAdd(&s_m, 1);
            if (p < SCAP) {
                const int idx = s0 + tid + 256 * j;   // batch-local pixel idx
                skey[p] = ((unsigned long long)v[j] << 32)
                        | (unsigned)(HWn - idx);      // smaller idx => bigger key
            }
        }
    }
    __syncthreads();
    const int M = (s_m < SCAP) ? s_m : SCAP;

    // ---- rank-sort (keys unique: strict order) + write DESC-sorted ----
    // grid-stride: M (~302) exceeds blockDim (256)!
    unsigned long long* cd = g_ckey + (size_t)blk * SCAP;
    for (int i = tid; i < M; i += 256) {
        const unsigned long long mk = skey[i];
        int rank = 0;
        #pragma unroll 4
        for (int j = 0; j < M; ++j) rank += (skey[j] > mk);
        cd[rank] = mk;
    }
    if (tid == 0) g_ccnt[blk] = M;
}

// ---------------------------------------------------------------------------
// Stage 2: 128 blocks (one per segment) x 256 threads. Each block loads its
// batch's 8 DESC-sorted lists into SMEM (24 KB, zero-padded), then for each
// own-list element with pos < min(cnt, 300): exact global rank = pos + sum
// over the 7 other lists of count(key > x) via binary search (9 dependent
// LDS probes per list; unique keys). rank < 300 -> gather payload from the
// L2-resident maps and write the output row. Safety: an element whose true
// global rank >= 300 either sees its computed rank >= 300 directly, or some
// competitor's whole segment (>= 300 survivors) sits above it — same result.
// jax.lax.top_k tie rule (desc value, ties -> lower index) is in the key
// low word.
// ---------------------------------------------------------------------------
__global__ __launch_bounds__(256) void topk_final(float* __restrict__ out)
{
    const int blk = blockIdx.x;             // 0..127
    const int b   = blk >> 3;
    const int sg  = blk & 7;
    const int tid = threadIdx.x;

    __shared__ unsigned long long lst[SEGS * SCAP];
    __shared__ int cnt[SEGS];

    if (tid < SEGS) cnt[tid] = g_ccnt[b * SEGS + tid];
    __syncthreads();

    for (int slot = tid; slot < SEGS * SCAP; slot += 256) {
        const int Li  = slot / SCAP;
        const int pos = slot - Li * SCAP;
        lst[slot] = (pos < cnt[Li])
                  ? g_ckey[(size_t)(b * SEGS + Li) * SCAP + pos] : 0ULL;
    }
    __syncthreads();

    const int myc = cnt[sg] < Kn ? cnt[sg] : Kn;   // pos >= 300 can't win
    for (int pos = tid; pos < myc; pos += 256) {
        const unsigned long long xk = lst[sg * SCAP + pos];

        int rank = pos;
        #pragma unroll
        for (int L2 = 0; L2 < SEGS; ++L2) {
            if (L2 == sg) continue;
            const unsigned long long* ls = lst + L2 * SCAP;
            int lo = 0, hi = cnt[L2];
            while (lo < hi) {                   // count of keys > xk (desc list)
                const int mid = (lo + hi) >> 1;
                if (ls[mid] > xk) lo = mid + 1; else hi = mid;
            }
            rank += lo;
        }

        if (rank < Kn) {
            const int k = HWn - (int)(unsigned)xk;   // batch-local pixel idx
            float* o = out + ((size_t)b * Kn + rank) * 3;
            o[0] = (float)(k / Hn) + g_reg0[b * HWn + k];
            o[1] = (float)(k % Hn) + g_reg1[b * HWn + k];
            o[2] = g_conf[b * HWn + k];
        }
    }
}

// ---------------------------------------------------------------------------
extern "C" void kernel_launch(void* const* d_in, const int* in_sizes, int n_in,
                              void* d_out, int out_size)
{
    const float* x      = (const float*)d_in[0];  // (16,256,128,128)
    const float* w_reg  = (const float*)d_in[1];  // (2,256)
    const float* b_reg  = (const float*)d_in[2];  // (2,)
    const float* w_conf = (const float*)d_in[3];  // (1,256)
    const float* b_conf = (const float*)d_in[4];  // (1,)
    float*       out    = (float*)d_out;          // (16,300,3)

    score_kernel<<<128, 512>>>(x, w_reg, b_reg, w_conf, b_conf);
    topk_stage1<<<Bn * SEGS, 256>>>();
    topk_final<<<Bn * SEGS, 256>>>(out);
}